// round 14
// baseline (speedup 1.0000x reference)
#include <cuda_runtime.h>
#include <cuda_fp16.h>
#include <cstdint>
#include <cstddef>

#define TPB 128
#define NEG_SLOPE 0.01f
#define XSTRB 528                     /* X row stride bytes (256 fp16 + pad) */

/* smem byte offsets (per CTA: 70144 B) */
#define XHI_OFF 0
#define B1_OFF  67584
#define W2_OFF  68608
#define GR_OFF  69632
#define SMEM_TOTAL 70144

__device__ float g_H[(size_t)131072 * 256];
/* B-fragment layout: [widx][kc(16)][nt_g(32)][term(2)][lane(32)] x 8B = 256KB per widx */
__device__ __align__(16) uint8_t g_Wfrag[3 * 262144];

__device__ __forceinline__ uint32_t smem_u32(const void* p) {
    uint32_t a;
    asm("{ .reg .u64 t; cvta.to.shared.u64 t, %1; cvt.u32.u64 %0, t; }" : "=r"(a) : "l"(p));
    return a;
}
__device__ __forceinline__ float lrelu(float x) {
    return fmaxf(x, 0.f) + NEG_SLOPE * fminf(x, 0.f);
}
__device__ __forceinline__ uint32_t pack_h2(float v0, float v1) {
    __half2 h = __floats2half2_rn(v0, v1);
    return *(uint32_t*)&h;
}
__device__ __forceinline__ void mma16816(float* c, const uint32_t* a, uint32_t b0, uint32_t b1) {
    asm("mma.sync.aligned.m16n8k16.row.col.f32.f16.f16.f32 "
        "{%0,%1,%2,%3},{%4,%5,%6,%7},{%8,%9},{%0,%1,%2,%3};"
        : "+f"(c[0]), "+f"(c[1]), "+f"(c[2]), "+f"(c[3])
        : "r"(a[0]), "r"(a[1]), "r"(a[2]), "r"(a[3]), "r"(b0), "r"(b1));
}
#define LDM_X4(r, a) \
    asm volatile("ldmatrix.sync.aligned.m8n8.x4.shared.b16 {%0,%1,%2,%3}, [%4];" \
        : "=r"((r)[0]), "=r"((r)[1]), "=r"((r)[2]), "=r"((r)[3]) : "r"(a))

/* ---- prep: W[rows<=256][256] fp32 -> fp16 hi/lo B-register fragments ---- */
__global__ void prep_frag(const float* __restrict__ W, int which, int wrows) {
    int e = blockIdx.x * blockDim.x + threadIdx.x;    /* 0..32767 */
    int lane = e & 31, term = (e >> 5) & 1, nt = (e >> 6) & 31, kc = e >> 11;
    int n = nt * 8 + (lane >> 2);
    int k0 = kc * 16 + 2 * (lane & 3);
    float v0 = 0.f, v1 = 0.f, v8 = 0.f, v9 = 0.f;
    if (n < wrows) {
        const float* src = W + (size_t)n * 256 + k0;
        v0 = src[0]; v1 = src[1]; v8 = src[8]; v9 = src[9];
    }
    uint32_t b0, b1;
    if (term == 0) {
        b0 = pack_h2(v0, v1);
        b1 = pack_h2(v8, v9);
    } else {
        __half2 h0 = __floats2half2_rn(v0, v1); float2 f0 = __half22float2(h0);
        __half2 h1 = __floats2half2_rn(v8, v9); float2 f1 = __half22float2(h1);
        b0 = pack_h2(v0 - f0.x, v1 - f0.y);
        b1 = pack_h2(v8 - f1.x, v9 - f1.y);
    }
    size_t off = ((size_t)which << 18) + (size_t)(((kc * 32 + nt) * 2 + term) << 8) + (lane << 3);
    *(uint2*)(g_Wfrag + off) = make_uint2(b0, b1);
}

/* PASS 0: blocks [0,nbB) bond head, [nbB,..) stems L1 -> g_H | PASS 1: stems L2
   128 threads, 4 warps (2wm x 2wn), warp tile M64 x N64, acc 128 regs. */
template<int PASS>
__global__ void __launch_bounds__(TPB, 2)
mlp_kernel(const float* __restrict__ atom,
           const float* __restrict__ b_b1, const float* __restrict__ w_b2,
           const float* __restrict__ b_b2, const float* __restrict__ b_s1,
           const float* __restrict__ b_s2, const int* __restrict__ slices,
           const int* __restrict__ bd_b, const int* __restrict__ bonds,
           const int* __restrict__ st_b, const int* __restrict__ st_a,
           float* __restrict__ out_bond, float* __restrict__ out_stem, int nbB) {
    constexpr int NH = (PASS == 1) ? 1 : 2;
    constexpr int NITER = NH * 16;
    extern __shared__ char sm[];
    uint32_t sb = smem_u32(sm);
    int tid = threadIdx.x, lid = tid & 31, wid = tid >> 5;   /* wid 0..3 */
    int wm = wid & 1, wn = wid >> 1;                          /* wn 0..1 */
    int mode = (PASS == 1) ? 2 : ((int)blockIdx.x < nbB ? 1 : 0);
    int row_base = (PASS == 1) ? blockIdx.x * 128
                 : (mode == 1 ? blockIdx.x * 128 : (blockIdx.x - nbB) * 128);
    int widx = (PASS == 1) ? 2 : (mode == 1 ? 0 : 1);
    const uint8_t* wbase = g_Wfrag + ((size_t)widx << 18) + (wn << 12) + (lid << 3);

    int*   grow = (int*)(sm + GR_OFF);
    float* b1s  = (float*)(sm + B1_OFF);
    float* w2s  = (float*)(sm + W2_OFF);

    {
        int r = row_base + tid, g;
        if (PASS == 1)       g = r;
        else if (mode == 1)  { int bd = r >> 1; g = slices[bd_b[bd]] + bonds[2 * bd + (r & 1)]; }
        else                 g = slices[st_b[r]] + st_a[r];
        grow[tid] = g;
    }
    if (PASS == 1) {
        b1s[tid] = (tid < 105) ? b_s2[tid] : 0.f;
        b1s[tid + 128] = 0.f;
    } else if (mode == 1) {
        b1s[tid] = b_b1[tid];       b1s[tid + 128] = b_b1[tid + 128];
        w2s[tid] = w_b2[tid];       w2s[tid + 128] = w_b2[tid + 128];
    } else {
        b1s[tid] = b_s1[tid];       b1s[tid + 128] = b_s1[tid + 128];
    }
    __syncthreads();

    /* ---- X gather + fp16-hi store: thread = (row pair, half) ---- */
    {
        const float* Asrc = (PASS == 1) ? (const float*)g_H : atom;
#pragma unroll
        for (int rr = 0; rr < 2; rr++) {
            int row = (tid >> 1) + rr * 64, h = tid & 1;
            const float4* src = (const float4*)(Asrc + (size_t)grow[row] * 256 + h * 128);
            char* xh = sm + XHI_OFF + row * XSTRB + h * 256;
#pragma unroll
            for (int q = 0; q < 32; q++) {
                float4 v = src[q];
                *(uint2*)(xh + q * 8) = make_uint2(pack_h2(v.x, v.y), pack_h2(v.z, v.w));
            }
        }
    }
    __syncthreads();    /* X visible; NO further mainloop barriers */

    float acc[4][8][4];
#pragma unroll
    for (int mt = 0; mt < 4; mt++)
#pragma unroll
        for (int nt = 0; nt < 8; nt++)
#pragma unroll
            for (int j = 0; j < 4; j++) acc[mt][nt][j] = 0.f;
    float ybond[8];
#pragma unroll
    for (int i = 0; i < 8; i++) ybond[i] = 0.f;

    int qr = lid >> 2, qc = lid & 3;
    uint32_t xab = sb + XHI_OFF + (uint32_t)(wm * 64 + (lid & 15)) * XSTRB + ((lid >> 4) << 4);

    /* B hi-fragment regs: 8 nt */
    uint2 Bc[8];
#pragma unroll
    for (int nt = 0; nt < 8; nt++)
        Bc[nt] = *(const uint2*)(wbase + nt * 512);

#pragma unroll 1
    for (int nh = 0; nh < NH; nh++) {
#pragma unroll 2
        for (int kc = 0; kc < 16; kc++) {
            int it = nh * 16 + kc;
            uint2 Bn[8];
            uint32_t ah[4];
            LDM_X4(ah, xab + kc * 32);
#pragma unroll
            for (int nt = 0; nt < 8; nt++)
                mma16816(acc[0][nt], ah, Bc[nt].x, Bc[nt].y);
            if (it + 1 < NITER) {
                int it2 = it + 1;
                const uint8_t* p = wbase + (size_t)((it2 & 15) << 14) + (size_t)((it2 >> 4) << 13);
#pragma unroll
                for (int nt = 0; nt < 8; nt++)
                    Bn[nt] = *(const uint2*)(p + nt * 512);
            }
#pragma unroll
            for (int mt = 1; mt < 4; mt++) {
                LDM_X4(ah, xab + mt * (16 * XSTRB) + kc * 32);
#pragma unroll
                for (int nt = 0; nt < 8; nt++)
                    mma16816(acc[mt][nt], ah, Bc[nt].x, Bc[nt].y);
            }
            if (it + 1 < NITER) {
#pragma unroll
                for (int i = 0; i < 8; i++) Bc[i] = Bn[i];
            }
        }
        /* ---- half-epilogue on N-half nh (cols nh*128 + wn*64 + nt*8 + 2qc) ---- */
        if (PASS == 0 && mode == 1) {
#pragma unroll
            for (int mt = 0; mt < 4; mt++)
#pragma unroll
                for (int jr = 0; jr < 2; jr++) {
                    float s = 0.f;
#pragma unroll
                    for (int nt = 0; nt < 8; nt++) {
                        int c = nh * 128 + wn * 64 + nt * 8 + 2 * qc;
                        s += lrelu(acc[mt][nt][2 * jr]     + b1s[c])     * w2s[c];
                        s += lrelu(acc[mt][nt][2 * jr + 1] + b1s[c + 1]) * w2s[c + 1];
                    }
                    ybond[mt * 2 + jr] += s;
                }
        } else if (PASS == 0) { /* stems L1 */
#pragma unroll
            for (int mt = 0; mt < 4; mt++)
#pragma unroll
                for (int jr = 0; jr < 2; jr++) {
                    size_t row = (size_t)row_base + wm * 64 + mt * 16 + qr + 8 * jr;
#pragma unroll
                    for (int nt = 0; nt < 8; nt++) {
                        int c = nh * 128 + wn * 64 + nt * 8 + 2 * qc;
                        float v0 = lrelu(acc[mt][nt][2 * jr]     + b1s[c]);
                        float v1 = lrelu(acc[mt][nt][2 * jr + 1] + b1s[c + 1]);
                        *(float2*)(g_H + row * 256 + c) = make_float2(v0, v1);
                    }
                }
        } else { /* PASS 1: single sweep, N=128, valid 105 */
#pragma unroll
            for (int mt = 0; mt < 4; mt++)
#pragma unroll
                for (int jr = 0; jr < 2; jr++) {
                    size_t row = (size_t)row_base + wm * 64 + mt * 16 + qr + 8 * jr;
#pragma unroll
                    for (int nt = 0; nt < 8; nt++) {
                        int c = wn * 64 + nt * 8 + 2 * qc;
                        if (c < 105)
                            out_stem[row * 105 + c] = acc[mt][nt][2 * jr] + b1s[c];
                        if (c + 1 < 105)
                            out_stem[row * 105 + c + 1] = acc[mt][nt][2 * jr + 1] + b1s[c + 1];
                    }
                }
        }
        if (nh == 0 && NH == 2) {
#pragma unroll
            for (int mt = 0; mt < 4; mt++)
#pragma unroll
                for (int nt = 0; nt < 8; nt++)
#pragma unroll
                    for (int j = 0; j < 4; j++) acc[mt][nt][j] = 0.f;
        }
    }

    /* ---- bond final reduce across the 2 wn groups ---- */
    if (PASS == 0 && mode == 1) {
        __syncthreads();
        float* ysm = (float*)(sm + XHI_OFF);   /* [2 wn][128 rows] */
#pragma unroll
        for (int mt = 0; mt < 4; mt++)
#pragma unroll
            for (int jr = 0; jr < 2; jr++) {
                float s = ybond[mt * 2 + jr];
                s += __shfl_xor_sync(0xffffffffu, s, 1);
                s += __shfl_xor_sync(0xffffffffu, s, 2);
                if (qc == 0)
                    ysm[wn * 128 + wm * 64 + mt * 16 + qr + 8 * jr] = s;
            }
        __syncthreads();
        {
            float y = ysm[tid] + ysm[128 + tid];
            float y2 = __shfl_down_sync(0xffffffffu, y, 1);
            if (!(tid & 1))
                out_bond[(row_base + tid) >> 1] = 0.5f * (y + y2) + b_b2[0];
        }
    }
}

extern "C" void kernel_launch(void* const* d_in, const int* in_sizes, int n_in,
                              void* d_out, int out_size) {
    const float* atom = (const float*)d_in[0];
    const float* mol  = (const float*)d_in[1];
    const float* w_s1 = (const float*)d_in[2];
    const float* b_s1 = (const float*)d_in[3];
    const float* w_s2 = (const float*)d_in[4];
    const float* b_s2 = (const float*)d_in[5];
    const float* w_b1 = (const float*)d_in[6];
    const float* b_b1 = (const float*)d_in[7];
    const float* w_b2 = (const float*)d_in[8];
    const float* b_b2 = (const float*)d_in[9];
    const int* slices = (const int*)d_in[10];
    const int* st_b   = (const int*)d_in[11];
    const int* st_a   = (const int*)d_in[12];
    const int* bonds  = (const int*)d_in[13];
    const int* bd_b   = (const int*)d_in[14];

    int n_stems = in_sizes[11];
    int n_mol   = in_sizes[1];
    int n_bonds = in_sizes[14];

    float* out      = (float*)d_out;
    float* out_stem = out;
    float* out_mol  = out + (size_t)n_stems * 105;
    float* out_bond = out_mol + n_mol;

    cudaFuncSetAttribute(mlp_kernel<0>, cudaFuncAttributeMaxDynamicSharedMemorySize, SMEM_TOTAL);
    cudaFuncSetAttribute(mlp_kernel<1>, cudaFuncAttributeMaxDynamicSharedMemorySize, SMEM_TOTAL);

    cudaMemcpyAsync(out_mol, mol, (size_t)n_mol * sizeof(float), cudaMemcpyDeviceToDevice);

    prep_frag<<<128, 256>>>(w_b1, 0, 256);
    prep_frag<<<128, 256>>>(w_s1, 1, 256);
    prep_frag<<<128, 256>>>(w_s2, 2, 105);

    int nbB = (2 * n_bonds) / 128;
    int nsB = n_stems / 128;
    mlp_kernel<0><<<nbB + nsB, TPB, SMEM_TOTAL>>>(
        atom, b_b1, w_b2, b_b2, b_s1, b_s2, slices, bd_b, bonds, st_b, st_a,
        out_bond, out_stem, nbB);
    mlp_kernel<1><<<nsB, TPB, SMEM_TOTAL>>>(
        atom, b_b1, w_b2, b_b2, b_s1, b_s2, slices, bd_b, bonds, st_b, st_a,
        out_bond, out_stem, 0);
}

// round 15
// speedup vs baseline: 1.0039x; 1.0039x over previous
#include <cuda_runtime.h>
#include <cuda_fp16.h>
#include <cstdint>
#include <cstddef>

#define TPB 256
#define NEG_SLOPE 0.01f
#define XSTRB 528                     /* X row stride bytes (256 fp16 + pad) */

/* smem byte offsets (per CTA: 70144 B -> 2 CTAs/SM) */
#define XHI_OFF 0
#define B1_OFF  67584
#define W2_OFF  68608
#define GR_OFF  69632
#define SMEM_TOTAL 70144

__device__ float g_H[(size_t)131072 * 256];
/* B-fragment layout: [widx][kc(16)][nt_g(32)][term(2)][lane(32)] x 8B = 256KB per widx */
__device__ __align__(16) uint8_t g_Wfrag[3 * 262144];

__device__ __forceinline__ uint32_t smem_u32(const void* p) {
    uint32_t a;
    asm("{ .reg .u64 t; cvta.to.shared.u64 t, %1; cvt.u32.u64 %0, t; }" : "=r"(a) : "l"(p));
    return a;
}
__device__ __forceinline__ float lrelu(float x) {
    return fmaxf(x, 0.f) + NEG_SLOPE * fminf(x, 0.f);
}
__device__ __forceinline__ uint32_t pack_h2(float v0, float v1) {
    __half2 h = __floats2half2_rn(v0, v1);
    return *(uint32_t*)&h;
}
__device__ __forceinline__ void mma16816(float* c, const uint32_t* a, uint32_t b0, uint32_t b1) {
    asm("mma.sync.aligned.m16n8k16.row.col.f32.f16.f16.f32 "
        "{%0,%1,%2,%3},{%4,%5,%6,%7},{%8,%9},{%0,%1,%2,%3};"
        : "+f"(c[0]), "+f"(c[1]), "+f"(c[2]), "+f"(c[3])
        : "r"(a[0]), "r"(a[1]), "r"(a[2]), "r"(a[3]), "r"(b0), "r"(b1));
}
#define LDM_X4(r, a) \
    asm volatile("ldmatrix.sync.aligned.m8n8.x4.shared.b16 {%0,%1,%2,%3}, [%4];" \
        : "=r"((r)[0]), "=r"((r)[1]), "=r"((r)[2]), "=r"((r)[3]) : "r"(a))

/* ---- prep: W[rows<=256][256] fp32 -> fp16 hi/lo B-register fragments ---- */
__global__ void prep_frag(const float* __restrict__ W, int which, int wrows) {
    int e = blockIdx.x * blockDim.x + threadIdx.x;    /* 0..32767 */
    int lane = e & 31, term = (e >> 5) & 1, nt = (e >> 6) & 31, kc = e >> 11;
    int n = nt * 8 + (lane >> 2);
    int k0 = kc * 16 + 2 * (lane & 3);
    float v0 = 0.f, v1 = 0.f, v8 = 0.f, v9 = 0.f;
    if (n < wrows) {
        const float* src = W + (size_t)n * 256 + k0;
        v0 = src[0]; v1 = src[1]; v8 = src[8]; v9 = src[9];
    }
    uint32_t b0, b1;
    if (term == 0) {
        b0 = pack_h2(v0, v1);
        b1 = pack_h2(v8, v9);
    } else {
        __half2 h0 = __floats2half2_rn(v0, v1); float2 f0 = __half22float2(h0);
        __half2 h1 = __floats2half2_rn(v8, v9); float2 f1 = __half22float2(h1);
        b0 = pack_h2(v0 - f0.x, v1 - f0.y);
        b1 = pack_h2(v8 - f1.x, v9 - f1.y);
    }
    size_t off = ((size_t)which << 18) + (size_t)(((kc * 32 + nt) * 2 + term) << 8) + (lane << 3);
    *(uint2*)(g_Wfrag + off) = make_uint2(b0, b1);
}

/* PASS 0: blocks [0,nbB) bond head, [nbB,..) stems L1 -> g_H | PASS 1: stems L2 */
template<int PASS>
__global__ void __launch_bounds__(TPB, 2)
mlp_kernel(const float* __restrict__ atom,
           const float* __restrict__ b_b1, const float* __restrict__ w_b2,
           const float* __restrict__ b_b2, const float* __restrict__ b_s1,
           const float* __restrict__ b_s2, const int* __restrict__ slices,
           const int* __restrict__ bd_b, const int* __restrict__ bonds,
           const int* __restrict__ st_b, const int* __restrict__ st_a,
           float* __restrict__ out_bond, float* __restrict__ out_stem, int nbB) {
    constexpr int NH = (PASS == 1) ? 1 : 2;
    constexpr int NITER = NH * 16;
    extern __shared__ char sm[];
    uint32_t sb = smem_u32(sm);
    int tid = threadIdx.x, lid = tid & 31, wid = tid >> 5;
    int wm = wid & 1, wn = wid >> 1;
    int mode = (PASS == 1) ? 2 : ((int)blockIdx.x < nbB ? 1 : 0);
    int row_base = (PASS == 1) ? blockIdx.x * 128
                 : (mode == 1 ? blockIdx.x * 128 : (blockIdx.x - nbB) * 128);
    int widx = (PASS == 1) ? 2 : (mode == 1 ? 0 : 1);
    const uint8_t* wbase = g_Wfrag + ((size_t)widx << 18) + (wn << 11) + (lid << 3);

    int*   grow = (int*)(sm + GR_OFF);
    float* b1s  = (float*)(sm + B1_OFF);
    float* w2s  = (float*)(sm + W2_OFF);

    if (tid < 128) {
        int r = row_base + tid, g;
        if (PASS == 1)       g = r;
        else if (mode == 1)  { int bd = r >> 1; g = slices[bd_b[bd]] + bonds[2 * bd + (r & 1)]; }
        else                 g = slices[st_b[r]] + st_a[r];
        grow[tid] = g;
    }
    if (PASS == 1) b1s[tid] = (tid < 105) ? b_s2[tid] : 0.f;
    else           b1s[tid] = (mode == 1) ? b_b1[tid] : b_s1[tid];
    if (PASS == 0 && mode == 1) w2s[tid] = w_b2[tid];
    __syncthreads();

    /* ---- X gather + fp16-hi store: thread = (row, half = 128 floats) ---- */
    {
        const float* Asrc = (PASS == 1) ? (const float*)g_H : atom;
        int row = tid >> 1, h = tid & 1;
        const float4* src = (const float4*)(Asrc + (size_t)grow[row] * 256 + h * 128);
        char* xh = sm + XHI_OFF + row * XSTRB + h * 256;
#pragma unroll
        for (int q = 0; q < 32; q++) {
            float4 v = src[q];
            *(uint2*)(xh + q * 8) = make_uint2(pack_h2(v.x, v.y), pack_h2(v.z, v.w));
        }
    }
    __syncthreads();    /* X visible; NO further mainloop barriers */

    float acc[4][4][4];
#pragma unroll
    for (int mt = 0; mt < 4; mt++)
#pragma unroll
        for (int nt = 0; nt < 4; nt++)
#pragma unroll
            for (int j = 0; j < 4; j++) acc[mt][nt][j] = 0.f;
    float ybond[8];
#pragma unroll
    for (int i = 0; i < 8; i++) ybond[i] = 0.f;

    int qr = lid >> 2, qc = lid & 3;
    uint32_t xab = sb + XHI_OFF + (uint32_t)(wm * 64 + (lid & 15)) * XSTRB + ((lid >> 4) << 4);

    /* double-buffered fragments: A (4 mt x 4 regs) and B (4 nt) */
    uint32_t Ac[4][4], An[4][4];
    uint2 Bc[4], Bn[4];
#pragma unroll
    for (int mt = 0; mt < 4; mt++)
        LDM_X4(Ac[mt], xab + mt * (16 * XSTRB));
#pragma unroll
    for (int nt = 0; nt < 4; nt++)
        Bc[nt] = *(const uint2*)(wbase + nt * 512);

#pragma unroll 1
    for (int nh = 0; nh < NH; nh++) {
#pragma unroll 2
        for (int kc = 0; kc < 16; kc++) {
            int it = nh * 16 + kc;
            if (it + 1 < NITER) {
                int it2 = it + 1, kc2 = it2 & 15;
#pragma unroll
                for (int mt = 0; mt < 4; mt++)
                    LDM_X4(An[mt], xab + mt * (16 * XSTRB) + kc2 * 32);
                const uint8_t* p = wbase + (size_t)(kc2 << 14) + (size_t)((it2 >> 4) << 13);
#pragma unroll
                for (int nt = 0; nt < 4; nt++)
                    Bn[nt] = *(const uint2*)(p + nt * 512);
            }
#pragma unroll
            for (int mt = 0; mt < 4; mt++)
#pragma unroll
                for (int nt = 0; nt < 4; nt++)
                    mma16816(acc[mt][nt], Ac[mt], Bc[nt].x, Bc[nt].y);
            if (it + 1 < NITER) {
#pragma unroll
                for (int mt = 0; mt < 4; mt++)
#pragma unroll
                    for (int j = 0; j < 4; j++) Ac[mt][j] = An[mt][j];
#pragma unroll
                for (int nt = 0; nt < 4; nt++) Bc[nt] = Bn[nt];
            }
        }
        /* ---- half-epilogue on N-half nh ---- */
        if (PASS == 0 && mode == 1) {
#pragma unroll
            for (int mt = 0; mt < 4; mt++)
#pragma unroll
                for (int jr = 0; jr < 2; jr++) {
                    float s = 0.f;
#pragma unroll
                    for (int nt = 0; nt < 4; nt++) {
                        int c = nh * 128 + wn * 32 + nt * 8 + 2 * qc;
                        s += lrelu(acc[mt][nt][2 * jr]     + b1s[c])     * w2s[c];
                        s += lrelu(acc[mt][nt][2 * jr + 1] + b1s[c + 1]) * w2s[c + 1];
                    }
                    ybond[mt * 2 + jr] += s;
                }
        } else if (PASS == 0) { /* stems L1 */
#pragma unroll
            for (int mt = 0; mt < 4; mt++)
#pragma unroll
                for (int jr = 0; jr < 2; jr++) {
                    size_t row = (size_t)row_base + wm * 64 + mt * 16 + qr + 8 * jr;
#pragma unroll
                    for (int nt = 0; nt < 4; nt++) {
                        int c = nh * 128 + wn * 32 + nt * 8 + 2 * qc;
                        float v0 = lrelu(acc[mt][nt][2 * jr]     + b1s[c]);
                        float v1 = lrelu(acc[mt][nt][2 * jr + 1] + b1s[c + 1]);
                        *(float2*)(g_H + row * 256 + c) = make_float2(v0, v1);
                    }
                }
        } else { /* PASS 1 */
#pragma unroll
            for (int mt = 0; mt < 4; mt++)
#pragma unroll
                for (int jr = 0; jr < 2; jr++) {
                    size_t row = (size_t)row_base + wm * 64 + mt * 16 + qr + 8 * jr;
#pragma unroll
                    for (int nt = 0; nt < 4; nt++) {
                        int c = wn * 32 + nt * 8 + 2 * qc;
                        if (c < 105)
                            out_stem[row * 105 + c] = acc[mt][nt][2 * jr] + b1s[c];
                        if (c + 1 < 105)
                            out_stem[row * 105 + c + 1] = acc[mt][nt][2 * jr + 1] + b1s[c + 1];
                    }
                }
        }
        if (nh == 0 && NH == 2) {
#pragma unroll
            for (int mt = 0; mt < 4; mt++)
#pragma unroll
                for (int nt = 0; nt < 4; nt++)
#pragma unroll
                    for (int j = 0; j < 4; j++) acc[mt][nt][j] = 0.f;
        }
    }

    /* ---- bond final reduce across warps ---- */
    if (PASS == 0 && mode == 1) {
        __syncthreads();
        float* ysm = (float*)(sm + XHI_OFF);   /* reuse X area: [4 wn][128 rows] */
#pragma unroll
        for (int mt = 0; mt < 4; mt++)
#pragma unroll
            for (int jr = 0; jr < 2; jr++) {
                float s = ybond[mt * 2 + jr];
                s += __shfl_xor_sync(0xffffffffu, s, 1);
                s += __shfl_xor_sync(0xffffffffu, s, 2);
                if (qc == 0)
                    ysm[wn * 128 + wm * 64 + mt * 16 + qr + 8 * jr] = s;
            }
        __syncthreads();
        if (tid < 128) {
            float y = ysm[tid] + ysm[128 + tid] + ysm[256 + tid] + ysm[384 + tid];
            float y2 = __shfl_down_sync(0xffffffffu, y, 1);
            if (!(tid & 1))
                out_bond[(row_base + tid) >> 1] = 0.5f * (y + y2) + b_b2[0];
        }
    }
}

extern "C" void kernel_launch(void* const* d_in, const int* in_sizes, int n_in,
                              void* d_out, int out_size) {
    const float* atom = (const float*)d_in[0];
    const float* mol  = (const float*)d_in[1];
    const float* w_s1 = (const float*)d_in[2];
    const float* b_s1 = (const float*)d_in[3];
    const float* w_s2 = (const float*)d_in[4];
    const float* b_s2 = (const float*)d_in[5];
    const float* w_b1 = (const float*)d_in[6];
    const float* b_b1 = (const float*)d_in[7];
    const float* w_b2 = (const float*)d_in[8];
    const float* b_b2 = (const float*)d_in[9];
    const int* slices = (const int*)d_in[10];
    const int* st_b   = (const int*)d_in[11];
    const int* st_a   = (const int*)d_in[12];
    const int* bonds  = (const int*)d_in[13];
    const int* bd_b   = (const int*)d_in[14];

    int n_stems = in_sizes[11];
    int n_mol   = in_sizes[1];
    int n_bonds = in_sizes[14];

    float* out      = (float*)d_out;
    float* out_stem = out;
    float* out_mol  = out + (size_t)n_stems * 105;
    float* out_bond = out_mol + n_mol;

    cudaFuncSetAttribute(mlp_kernel<0>, cudaFuncAttributeMaxDynamicSharedMemorySize, SMEM_TOTAL);
    cudaFuncSetAttribute(mlp_kernel<1>, cudaFuncAttributeMaxDynamicSharedMemorySize, SMEM_TOTAL);

    cudaMemcpyAsync(out_mol, mol, (size_t)n_mol * sizeof(float), cudaMemcpyDeviceToDevice);

    prep_frag<<<128, 256>>>(w_b1, 0, 256);
    prep_frag<<<128, 256>>>(w_s1, 1, 256);
    prep_frag<<<128, 256>>>(w_s2, 2, 105);

    int nbB = (2 * n_bonds) / 128;
    int nsB = n_stems / 128;
    mlp_kernel<0><<<nbB + nsB, TPB, SMEM_TOTAL>>>(
        atom, b_b1, w_b2, b_b2, b_s1, b_s2, slices, bd_b, bonds, st_b, st_a,
        out_bond, out_stem, nbB);
    mlp_kernel<1><<<nsB, TPB, SMEM_TOTAL>>>(
        atom, b_b1, w_b2, b_b2, b_s1, b_s2, slices, bd_b, bonds, st_b, st_a,
        out_bond, out_stem, 0);
}

// round 16
// speedup vs baseline: 1.0172x; 1.0132x over previous
#include <cuda_runtime.h>
#include <cuda_fp16.h>
#include <cstdint>
#include <cstddef>

#define TPB 256
#define NEG_SLOPE 0.01f
#define XSTRB 528                     /* X row stride bytes (256 fp16 + pad) */

/* smem byte offsets (per CTA: 70144 B -> 2 CTAs/SM) */
#define XHI_OFF 0
#define B1_OFF  67584
#define W2_OFF  68608
#define GR_OFF  69632
#define SMEM_TOTAL 70144

__device__ float g_H[(size_t)131072 * 256];
/* B-fragment layout: [widx][kc(16)][nt_g(32)][term(2)][lane(32)] x 8B = 256KB per widx */
__device__ __align__(16) uint8_t g_Wfrag[3 * 262144];

__device__ __forceinline__ uint32_t smem_u32(const void* p) {
    uint32_t a;
    asm("{ .reg .u64 t; cvta.to.shared.u64 t, %1; cvt.u32.u64 %0, t; }" : "=r"(a) : "l"(p));
    return a;
}
__device__ __forceinline__ float lrelu(float x) {
    return fmaxf(x, 0.f) + NEG_SLOPE * fminf(x, 0.f);
}
__device__ __forceinline__ uint32_t pack_h2(float v0, float v1) {
    __half2 h = __floats2half2_rn(v0, v1);
    return *(uint32_t*)&h;
}
__device__ __forceinline__ void mma16816(float* c, const uint32_t* a, uint32_t b0, uint32_t b1) {
    asm("mma.sync.aligned.m16n8k16.row.col.f32.f16.f16.f32 "
        "{%0,%1,%2,%3},{%4,%5,%6,%7},{%8,%9},{%0,%1,%2,%3};"
        : "+f"(c[0]), "+f"(c[1]), "+f"(c[2]), "+f"(c[3])
        : "r"(a[0]), "r"(a[1]), "r"(a[2]), "r"(a[3]), "r"(b0), "r"(b1));
}
#define LDM_X4(r, a) \
    asm volatile("ldmatrix.sync.aligned.m8n8.x4.shared.b16 {%0,%1,%2,%3}, [%4];" \
        : "=r"((r)[0]), "=r"((r)[1]), "=r"((r)[2]), "=r"((r)[3]) : "r"(a))

/* ---- prep: W[rows<=256][256] fp32 -> fp16 hi/lo B-register fragments ---- */
__global__ void prep_frag(const float* __restrict__ W, int which, int wrows) {
    int e = blockIdx.x * blockDim.x + threadIdx.x;    /* 0..32767 */
    int lane = e & 31, term = (e >> 5) & 1, nt = (e >> 6) & 31, kc = e >> 11;
    int n = nt * 8 + (lane >> 2);
    int k0 = kc * 16 + 2 * (lane & 3);
    float v0 = 0.f, v1 = 0.f, v8 = 0.f, v9 = 0.f;
    if (n < wrows) {
        const float* src = W + (size_t)n * 256 + k0;
        v0 = src[0]; v1 = src[1]; v8 = src[8]; v9 = src[9];
    }
    uint32_t b0, b1;
    if (term == 0) {
        b0 = pack_h2(v0, v1);
        b1 = pack_h2(v8, v9);
    } else {
        __half2 h0 = __floats2half2_rn(v0, v1); float2 f0 = __half22float2(h0);
        __half2 h1 = __floats2half2_rn(v8, v9); float2 f1 = __half22float2(h1);
        b0 = pack_h2(v0 - f0.x, v1 - f0.y);
        b1 = pack_h2(v8 - f1.x, v9 - f1.y);
    }
    size_t off = ((size_t)which << 18) + (size_t)(((kc * 32 + nt) * 2 + term) << 8) + (lane << 3);
    *(uint2*)(g_Wfrag + off) = make_uint2(b0, b1);
}

/* PASS 0: blocks [0,nbB) bond head, [nbB,..) stems L1 -> g_H | PASS 1: stems L2
   8 warps as 4wm x 2wn; warp tile M32 x N64 (2mt x 8nt), acc 64 regs. */
template<int PASS>
__global__ void __launch_bounds__(TPB, 2)
mlp_kernel(const float* __restrict__ atom,
           const float* __restrict__ b_b1, const float* __restrict__ w_b2,
           const float* __restrict__ b_b2, const float* __restrict__ b_s1,
           const float* __restrict__ b_s2, const int* __restrict__ slices,
           const int* __restrict__ bd_b, const int* __restrict__ bonds,
           const int* __restrict__ st_b, const int* __restrict__ st_a,
           float* __restrict__ out_bond, float* __restrict__ out_stem, int nbB) {
    constexpr int NH = (PASS == 1) ? 1 : 2;
    constexpr int NITER = NH * 16;
    extern __shared__ char sm[];
    uint32_t sb = smem_u32(sm);
    int tid = threadIdx.x, lid = tid & 31, wid = tid >> 5;
    int wm = wid & 3, wn = wid >> 2;      /* 4 x 2 warp grid */
    int mode = (PASS == 1) ? 2 : ((int)blockIdx.x < nbB ? 1 : 0);
    int row_base = (PASS == 1) ? blockIdx.x * 128
                 : (mode == 1 ? blockIdx.x * 128 : (blockIdx.x - nbB) * 128);
    int widx = (PASS == 1) ? 2 : (mode == 1 ? 0 : 1);
    /* nt_g = wn*8 + nt  ->  byte offset (wn*8+nt)*512 = wn*4096 + nt*512 */
    const uint8_t* wbase = g_Wfrag + ((size_t)widx << 18) + (wn << 12) + (lid << 3);

    int*   grow = (int*)(sm + GR_OFF);
    float* b1s  = (float*)(sm + B1_OFF);
    float* w2s  = (float*)(sm + W2_OFF);

    if (tid < 128) {
        int r = row_base + tid, g;
        if (PASS == 1)       g = r;
        else if (mode == 1)  { int bd = r >> 1; g = slices[bd_b[bd]] + bonds[2 * bd + (r & 1)]; }
        else                 g = slices[st_b[r]] + st_a[r];
        grow[tid] = g;
    }
    if (PASS == 1) b1s[tid] = (tid < 105) ? b_s2[tid] : 0.f;
    else           b1s[tid] = (mode == 1) ? b_b1[tid] : b_s1[tid];
    if (PASS == 0 && mode == 1) w2s[tid] = w_b2[tid];
    __syncthreads();

    /* ---- X gather + fp16-hi store: thread = (row, half = 128 floats) ---- */
    {
        const float* Asrc = (PASS == 1) ? (const float*)g_H : atom;
        int row = tid >> 1, h = tid & 1;
        const float4* src = (const float4*)(Asrc + (size_t)grow[row] * 256 + h * 128);
        char* xh = sm + XHI_OFF + row * XSTRB + h * 256;
#pragma unroll
        for (int q = 0; q < 32; q++) {
            float4 v = src[q];
            *(uint2*)(xh + q * 8) = make_uint2(pack_h2(v.x, v.y), pack_h2(v.z, v.w));
        }
    }
    __syncthreads();    /* X visible; NO further mainloop barriers */

    float acc[2][8][4];
#pragma unroll
    for (int mt = 0; mt < 2; mt++)
#pragma unroll
        for (int nt = 0; nt < 8; nt++)
#pragma unroll
            for (int j = 0; j < 4; j++) acc[mt][nt][j] = 0.f;
    float ybond[4];
#pragma unroll
    for (int i = 0; i < 4; i++) ybond[i] = 0.f;

    int qr = lid >> 2, qc = lid & 3;
    uint32_t xab = sb + XHI_OFF + (uint32_t)(wm * 32 + (lid & 15)) * XSTRB + ((lid >> 4) << 4);

    /* B hi-fragment regs: 8 nt */
    uint2 Bc[8];
#pragma unroll
    for (int nt = 0; nt < 8; nt++)
        Bc[nt] = *(const uint2*)(wbase + nt * 512);

#pragma unroll 1
    for (int nh = 0; nh < NH; nh++) {
#pragma unroll 2
        for (int kc = 0; kc < 16; kc++) {
            int it = nh * 16 + kc;
            uint2 Bn[8];
            uint32_t ah[4];
            LDM_X4(ah, xab + kc * 32);
#pragma unroll
            for (int nt = 0; nt < 8; nt++)
                mma16816(acc[0][nt], ah, Bc[nt].x, Bc[nt].y);
            if (it + 1 < NITER) {
                int it2 = it + 1;
                const uint8_t* p = wbase + (size_t)((it2 & 15) << 14) + (size_t)((it2 >> 4) << 13);
#pragma unroll
                for (int nt = 0; nt < 8; nt++)
                    Bn[nt] = *(const uint2*)(p + nt * 512);
            }
            {
                uint32_t ah1[4];
                LDM_X4(ah1, xab + 16 * XSTRB + kc * 32);
#pragma unroll
                for (int nt = 0; nt < 8; nt++)
                    mma16816(acc[1][nt], ah1, Bc[nt].x, Bc[nt].y);
            }
            if (it + 1 < NITER) {
#pragma unroll
                for (int i = 0; i < 8; i++) Bc[i] = Bn[i];
            }
        }
        /* ---- half-epilogue on N-half nh (cols nh*128 + wn*64 + nt*8 + 2qc) ---- */
        if (PASS == 0 && mode == 1) {
#pragma unroll
            for (int mt = 0; mt < 2; mt++)
#pragma unroll
                for (int jr = 0; jr < 2; jr++) {
                    float s = 0.f;
#pragma unroll
                    for (int nt = 0; nt < 8; nt++) {
                        int c = nh * 128 + wn * 64 + nt * 8 + 2 * qc;
                        s += lrelu(acc[mt][nt][2 * jr]     + b1s[c])     * w2s[c];
                        s += lrelu(acc[mt][nt][2 * jr + 1] + b1s[c + 1]) * w2s[c + 1];
                    }
                    ybond[mt * 2 + jr] += s;
                }
        } else if (PASS == 0) { /* stems L1 */
#pragma unroll
            for (int mt = 0; mt < 2; mt++)
#pragma unroll
                for (int jr = 0; jr < 2; jr++) {
                    size_t row = (size_t)row_base + wm * 32 + mt * 16 + qr + 8 * jr;
#pragma unroll
                    for (int nt = 0; nt < 8; nt++) {
                        int c = nh * 128 + wn * 64 + nt * 8 + 2 * qc;
                        float v0 = lrelu(acc[mt][nt][2 * jr]     + b1s[c]);
                        float v1 = lrelu(acc[mt][nt][2 * jr + 1] + b1s[c + 1]);
                        *(float2*)(g_H + row * 256 + c) = make_float2(v0, v1);
                    }
                }
        } else { /* PASS 1: single sweep, N=128, valid 105 */
#pragma unroll
            for (int mt = 0; mt < 2; mt++)
#pragma unroll
                for (int jr = 0; jr < 2; jr++) {
                    size_t row = (size_t)row_base + wm * 32 + mt * 16 + qr + 8 * jr;
#pragma unroll
                    for (int nt = 0; nt < 8; nt++) {
                        int c = wn * 64 + nt * 8 + 2 * qc;
                        if (c < 105)
                            out_stem[row * 105 + c] = acc[mt][nt][2 * jr] + b1s[c];
                        if (c + 1 < 105)
                            out_stem[row * 105 + c + 1] = acc[mt][nt][2 * jr + 1] + b1s[c + 1];
                    }
                }
        }
        if (nh == 0 && NH == 2) {
#pragma unroll
            for (int mt = 0; mt < 2; mt++)
#pragma unroll
                for (int nt = 0; nt < 8; nt++)
#pragma unroll
                    for (int j = 0; j < 4; j++) acc[mt][nt][j] = 0.f;
        }
    }

    /* ---- bond final reduce across the 2 wn groups ---- */
    if (PASS == 0 && mode == 1) {
        __syncthreads();
        float* ysm = (float*)(sm + XHI_OFF);   /* [2 wn][128 rows] */
#pragma unroll
        for (int mt = 0; mt < 2; mt++)
#pragma unroll
            for (int jr = 0; jr < 2; jr++) {
                float s = ybond[mt * 2 + jr];
                s += __shfl_xor_sync(0xffffffffu, s, 1);
                s += __shfl_xor_sync(0xffffffffu, s, 2);
                if (qc == 0)
                    ysm[wn * 128 + wm * 32 + mt * 16 + qr + 8 * jr] = s;
            }
        __syncthreads();
        if (tid < 128) {
            float y = ysm[tid] + ysm[128 + tid];
            float y2 = __shfl_down_sync(0xffffffffu, y, 1);
            if (!(tid & 1))
                out_bond[(row_base + tid) >> 1] = 0.5f * (y + y2) + b_b2[0];
        }
    }
}

extern "C" void kernel_launch(void* const* d_in, const int* in_sizes, int n_in,
                              void* d_out, int out_size) {
    const float* atom = (const float*)d_in[0];
    const float* mol  = (const float*)d_in[1];
    const float* w_s1 = (const float*)d_in[2];
    const float* b_s1 = (const float*)d_in[3];
    const float* w_s2 = (const float*)d_in[4];
    const float* b_s2 = (const float*)d_in[5];
    const float* w_b1 = (const float*)d_in[6];
    const float* b_b1 = (const float*)d_in[7];
    const float* w_b2 = (const float*)d_in[8];
    const float* b_b2 = (const float*)d_in[9];
    const int* slices = (const int*)d_in[10];
    const int* st_b   = (const int*)d_in[11];
    const int* st_a   = (const int*)d_in[12];
    const int* bonds  = (const int*)d_in[13];
    const int* bd_b   = (const int*)d_in[14];

    int n_stems = in_sizes[11];
    int n_mol   = in_sizes[1];
    int n_bonds = in_sizes[14];

    float* out      = (float*)d_out;
    float* out_stem = out;
    float* out_mol  = out + (size_t)n_stems * 105;
    float* out_bond = out_mol + n_mol;

    cudaFuncSetAttribute(mlp_kernel<0>, cudaFuncAttributeMaxDynamicSharedMemorySize, SMEM_TOTAL);
    cudaFuncSetAttribute(mlp_kernel<1>, cudaFuncAttributeMaxDynamicSharedMemorySize, SMEM_TOTAL);

    cudaMemcpyAsync(out_mol, mol, (size_t)n_mol * sizeof(float), cudaMemcpyDeviceToDevice);

    prep_frag<<<128, 256>>>(w_b1, 0, 256);
    prep_frag<<<128, 256>>>(w_s1, 1, 256);
    prep_frag<<<128, 256>>>(w_s2, 2, 105);

    int nbB = (2 * n_bonds) / 128;
    int nsB = n_stems / 128;
    mlp_kernel<0><<<nbB + nsB, TPB, SMEM_TOTAL>>>(
        atom, b_b1, w_b2, b_b2, b_s1, b_s2, slices, bd_b, bonds, st_b, st_a,
        out_bond, out_stem, nbB);
    mlp_kernel<1><<<nsB, TPB, SMEM_TOTAL>>>(
        atom, b_b1, w_b2, b_b2, b_s1, b_s2, slices, bd_b, bonds, st_b, st_a,
        out_bond, out_stem, 0);
}

// round 17
// speedup vs baseline: 1.2667x; 1.2453x over previous
#include <cuda_runtime.h>
#include <cuda_fp16.h>
#include <cstdint>
#include <cstddef>

#define TPB 256
#define NEG_SLOPE 0.01f
#define XSTRB 528                     /* X row stride bytes (256 fp16 + pad) */

/* smem byte offsets (per CTA: 70144 B -> 2 CTAs/SM) */
#define XHI_OFF 0
#define B1_OFF  67584
#define W2_OFF  68608
#define GR_OFF  69632
#define SMEM_TOTAL 70144

__device__ float g_H[(size_t)131072 * 256];
/* B-fragment layout: [widx][kc(16)][nt_g(32)][term(2)][lane(32)] x 8B = 256KB per widx */
__device__ __align__(16) uint8_t g_Wfrag[3 * 262144];

__device__ __forceinline__ uint32_t smem_u32(const void* p) {
    uint32_t a;
    asm("{ .reg .u64 t; cvta.to.shared.u64 t, %1; cvt.u32.u64 %0, t; }" : "=r"(a) : "l"(p));
    return a;
}
__device__ __forceinline__ float lrelu(float x) {
    return fmaxf(x, 0.f) + NEG_SLOPE * fminf(x, 0.f);
}
__device__ __forceinline__ uint32_t pack_h2(float v0, float v1) {
    __half2 h = __floats2half2_rn(v0, v1);
    return *(uint32_t*)&h;
}
__device__ __forceinline__ void mma16816(float* c, const uint32_t* a, uint32_t b0, uint32_t b1) {
    asm("mma.sync.aligned.m16n8k16.row.col.f32.f16.f16.f32 "
        "{%0,%1,%2,%3},{%4,%5,%6,%7},{%8,%9},{%0,%1,%2,%3};"
        : "+f"(c[0]), "+f"(c[1]), "+f"(c[2]), "+f"(c[3])
        : "r"(a[0]), "r"(a[1]), "r"(a[2]), "r"(a[3]), "r"(b0), "r"(b1));
}
#define LDM_X4(r, a) \
    asm volatile("ldmatrix.sync.aligned.m8n8.x4.shared.b16 {%0,%1,%2,%3}, [%4];" \
        : "=r"((r)[0]), "=r"((r)[1]), "=r"((r)[2]), "=r"((r)[3]) : "r"(a))

/* ---- prep: W[rows<=256][256] fp32 -> fp16 hi/lo B-register fragments ---- */
__global__ void prep_frag(const float* __restrict__ W, int which, int wrows) {
    int e = blockIdx.x * blockDim.x + threadIdx.x;    /* 0..32767 */
    int lane = e & 31, term = (e >> 5) & 1, nt = (e >> 6) & 31, kc = e >> 11;
    int n = nt * 8 + (lane >> 2);
    int k0 = kc * 16 + 2 * (lane & 3);
    float v0 = 0.f, v1 = 0.f, v8 = 0.f, v9 = 0.f;
    if (n < wrows) {
        const float* src = W + (size_t)n * 256 + k0;
        v0 = src[0]; v1 = src[1]; v8 = src[8]; v9 = src[9];
    }
    uint32_t b0, b1;
    if (term == 0) {
        b0 = pack_h2(v0, v1);
        b1 = pack_h2(v8, v9);
    } else {
        __half2 h0 = __floats2half2_rn(v0, v1); float2 f0 = __half22float2(h0);
        __half2 h1 = __floats2half2_rn(v8, v9); float2 f1 = __half22float2(h1);
        b0 = pack_h2(v0 - f0.x, v1 - f0.y);
        b1 = pack_h2(v8 - f1.x, v9 - f1.y);
    }
    size_t off = ((size_t)which << 18) + (size_t)(((kc * 32 + nt) * 2 + term) << 8) + (lane << 3);
    *(uint2*)(g_Wfrag + off) = make_uint2(b0, b1);
}

/* PASS 0: blocks [0,nbB) bond head, [nbB,..) stems L1 -> g_H | PASS 1: stems L2 */
template<int PASS>
__global__ void __launch_bounds__(TPB, 2)
mlp_kernel(const float* __restrict__ atom,
           const float* __restrict__ b_b1, const float* __restrict__ w_b2,
           const float* __restrict__ b_b2, const float* __restrict__ b_s1,
           const float* __restrict__ b_s2, const int* __restrict__ slices,
           const int* __restrict__ bd_b, const int* __restrict__ bonds,
           const int* __restrict__ st_b, const int* __restrict__ st_a,
           float* __restrict__ out_bond, float* __restrict__ out_stem, int nbB) {
    constexpr int NH = (PASS == 1) ? 1 : 2;
    constexpr int NITER = NH * 16;
    extern __shared__ char sm[];
    uint32_t sb = smem_u32(sm);
    int tid = threadIdx.x, lid = tid & 31, wid = tid >> 5;
    int wm = wid & 1, wn = wid >> 1;
    int mode = (PASS == 1) ? 2 : ((int)blockIdx.x < nbB ? 1 : 0);
    int row_base = (PASS == 1) ? blockIdx.x * 128
                 : (mode == 1 ? blockIdx.x * 128 : (blockIdx.x - nbB) * 128);
    int widx = (PASS == 1) ? 2 : (mode == 1 ? 0 : 1);
    const uint8_t* wbase = g_Wfrag + ((size_t)widx << 18) + (wn << 11) + (lid << 3);

    int*   grow = (int*)(sm + GR_OFF);
    float* b1s  = (float*)(sm + B1_OFF);
    float* w2s  = (float*)(sm + W2_OFF);

    if (tid < 128) {
        int r = row_base + tid, g;
        if (PASS == 1)       g = r;
        else if (mode == 1)  { int bd = r >> 1; g = slices[bd_b[bd]] + bonds[2 * bd + (r & 1)]; }
        else                 g = slices[st_b[r]] + st_a[r];
        grow[tid] = g;
    }
    if (PASS == 1) b1s[tid] = (tid < 105) ? b_s2[tid] : 0.f;
    else           b1s[tid] = (mode == 1) ? b_b1[tid] : b_s1[tid];
    if (PASS == 0 && mode == 1) w2s[tid] = w_b2[tid];
    __syncthreads();

    /* ---- X gather, warp-per-row coalesced: lane covers 32B of the 1KB row ---- */
    {
        const float* Asrc = (PASS == 1) ? (const float*)g_H : atom;
        int rbase = wid * 16;
#pragma unroll
        for (int rr = 0; rr < 16; rr++) {
            int row = rbase + rr;
            const float4* src = (const float4*)(Asrc + (size_t)grow[row] * 256) + lid * 2;
            float4 v0 = src[0], v1 = src[1];
            uint4 o = make_uint4(pack_h2(v0.x, v0.y), pack_h2(v0.z, v0.w),
                                 pack_h2(v1.x, v1.y), pack_h2(v1.z, v1.w));
            *(uint4*)(sm + XHI_OFF + row * XSTRB + lid * 16) = o;
        }
    }
    __syncthreads();    /* X visible; NO further mainloop barriers */

    float acc[4][4][4];
#pragma unroll
    for (int mt = 0; mt < 4; mt++)
#pragma unroll
        for (int nt = 0; nt < 4; nt++)
#pragma unroll
            for (int j = 0; j < 4; j++) acc[mt][nt][j] = 0.f;
    float ybond[8];
#pragma unroll
    for (int i = 0; i < 8; i++) ybond[i] = 0.f;

    int qr = lid >> 2, qc = lid & 3;
    uint32_t xab = sb + XHI_OFF + (uint32_t)(wm * 64 + (lid & 15)) * XSTRB + ((lid >> 4) << 4);

    /* B hi-fragment regs only (1-term) */
    uint2 Bc[4];
#pragma unroll
    for (int nt = 0; nt < 4; nt++)
        Bc[nt] = *(const uint2*)(wbase + nt * 512);

#pragma unroll 1
    for (int nh = 0; nh < NH; nh++) {
#pragma unroll 4
        for (int kc = 0; kc < 16; kc++) {
            int it = nh * 16 + kc;
            uint2 Bn[4];
            uint32_t ah[4];
            LDM_X4(ah, xab + kc * 32);
#pragma unroll
            for (int nt = 0; nt < 4; nt++)
                mma16816(acc[0][nt], ah, Bc[nt].x, Bc[nt].y);
            if (it + 1 < NITER) {
                int it2 = it + 1;
                const uint8_t* p = wbase + (size_t)((it2 & 15) << 14) + (size_t)((it2 >> 4) << 13);
#pragma unroll
                for (int nt = 0; nt < 4; nt++)
                    Bn[nt] = *(const uint2*)(p + nt * 512);
            }
#pragma unroll
            for (int mt = 1; mt < 4; mt++) {
                LDM_X4(ah, xab + mt * (16 * XSTRB) + kc * 32);
#pragma unroll
                for (int nt = 0; nt < 4; nt++)
                    mma16816(acc[mt][nt], ah, Bc[nt].x, Bc[nt].y);
            }
            if (it + 1 < NITER) {
#pragma unroll
                for (int i = 0; i < 4; i++) Bc[i] = Bn[i];
            }
        }
        /* ---- half-epilogue on N-half nh ---- */
        if (PASS == 0 && mode == 1) {
#pragma unroll
            for (int mt = 0; mt < 4; mt++)
#pragma unroll
                for (int jr = 0; jr < 2; jr++) {
                    float s = 0.f;
#pragma unroll
                    for (int nt = 0; nt < 4; nt++) {
                        int c = nh * 128 + wn * 32 + nt * 8 + 2 * qc;
                        s += lrelu(acc[mt][nt][2 * jr]     + b1s[c])     * w2s[c];
                        s += lrelu(acc[mt][nt][2 * jr + 1] + b1s[c + 1]) * w2s[c + 1];
                    }
                    ybond[mt * 2 + jr] += s;
                }
        } else if (PASS == 0) { /* stems L1 */
#pragma unroll
            for (int mt = 0; mt < 4; mt++)
#pragma unroll
                for (int jr = 0; jr < 2; jr++) {
                    size_t row = (size_t)row_base + wm * 64 + mt * 16 + qr + 8 * jr;
#pragma unroll
                    for (int nt = 0; nt < 4; nt++) {
                        int c = nh * 128 + wn * 32 + nt * 8 + 2 * qc;
                        float v0 = lrelu(acc[mt][nt][2 * jr]     + b1s[c]);
                        float v1 = lrelu(acc[mt][nt][2 * jr + 1] + b1s[c + 1]);
                        *(float2*)(g_H + row * 256 + c) = make_float2(v0, v1);
                    }
                }
        } else { /* PASS 1 */
#pragma unroll
            for (int mt = 0; mt < 4; mt++)
#pragma unroll
                for (int jr = 0; jr < 2; jr++) {
                    size_t row = (size_t)row_base + wm * 64 + mt * 16 + qr + 8 * jr;
#pragma unroll
                    for (int nt = 0; nt < 4; nt++) {
                        int c = wn * 32 + nt * 8 + 2 * qc;
                        if (c < 105)
                            out_stem[row * 105 + c] = acc[mt][nt][2 * jr] + b1s[c];
                        if (c + 1 < 105)
                            out_stem[row * 105 + c + 1] = acc[mt][nt][2 * jr + 1] + b1s[c + 1];
                    }
                }
        }
        if (nh == 0 && NH == 2) {
#pragma unroll
            for (int mt = 0; mt < 4; mt++)
#pragma unroll
                for (int nt = 0; nt < 4; nt++)
#pragma unroll
                    for (int j = 0; j < 4; j++) acc[mt][nt][j] = 0.f;
        }
    }

    /* ---- bond final reduce across warps ---- */
    if (PASS == 0 && mode == 1) {
        __syncthreads();
        float* ysm = (float*)(sm + XHI_OFF);   /* reuse X area: [4 wn][128 rows] */
#pragma unroll
        for (int mt = 0; mt < 4; mt++)
#pragma unroll
            for (int jr = 0; jr < 2; jr++) {
                float s = ybond[mt * 2 + jr];
                s += __shfl_xor_sync(0xffffffffu, s, 1);
                s += __shfl_xor_sync(0xffffffffu, s, 2);
                if (qc == 0)
                    ysm[wn * 128 + wm * 64 + mt * 16 + qr + 8 * jr] = s;
            }
        __syncthreads();
        if (tid < 128) {
            float y = ysm[tid] + ysm[128 + tid] + ysm[256 + tid] + ysm[384 + tid];
            float y2 = __shfl_down_sync(0xffffffffu, y, 1);
            if (!(tid & 1))
                out_bond[(row_base + tid) >> 1] = 0.5f * (y + y2) + b_b2[0];
        }
    }
}

extern "C" void kernel_launch(void* const* d_in, const int* in_sizes, int n_in,
                              void* d_out, int out_size) {
    const float* atom = (const float*)d_in[0];
    const float* mol  = (const float*)d_in[1];
    const float* w_s1 = (const float*)d_in[2];
    const float* b_s1 = (const float*)d_in[3];
    const float* w_s2 = (const float*)d_in[4];
    const float* b_s2 = (const float*)d_in[5];
    const float* w_b1 = (const float*)d_in[6];
    const float* b_b1 = (const float*)d_in[7];
    const float* w_b2 = (const float*)d_in[8];
    const float* b_b2 = (const float*)d_in[9];
    const int* slices = (const int*)d_in[10];
    const int* st_b   = (const int*)d_in[11];
    const int* st_a   = (const int*)d_in[12];
    const int* bonds  = (const int*)d_in[13];
    const int* bd_b   = (const int*)d_in[14];

    int n_stems = in_sizes[11];
    int n_mol   = in_sizes[1];
    int n_bonds = in_sizes[14];

    float* out      = (float*)d_out;
    float* out_stem = out;
    float* out_mol  = out + (size_t)n_stems * 105;
    float* out_bond = out_mol + n_mol;

    cudaFuncSetAttribute(mlp_kernel<0>, cudaFuncAttributeMaxDynamicSharedMemorySize, SMEM_TOTAL);
    cudaFuncSetAttribute(mlp_kernel<1>, cudaFuncAttributeMaxDynamicSharedMemorySize, SMEM_TOTAL);

    cudaMemcpyAsync(out_mol, mol, (size_t)n_mol * sizeof(float), cudaMemcpyDeviceToDevice);

    prep_frag<<<128, 256>>>(w_b1, 0, 256);
    prep_frag<<<128, 256>>>(w_s1, 1, 256);
    prep_frag<<<128, 256>>>(w_s2, 2, 105);

    int nbB = (2 * n_bonds) / 128;
    int nsB = n_stems / 128;
    mlp_kernel<0><<<nbB + nsB, TPB, SMEM_TOTAL>>>(
        atom, b_b1, w_b2, b_b2, b_s1, b_s2, slices, bd_b, bonds, st_b, st_a,
        out_bond, out_stem, nbB);
    mlp_kernel<1><<<nsB, TPB, SMEM_TOTAL>>>(
        atom, b_b1, w_b2, b_b2, b_s1, b_s2, slices, bd_b, bonds, st_b, st_a,
        out_bond, out_stem, 0);
}